// round 13
// baseline (speedup 1.0000x reference)
#include <cuda_runtime.h>
#include <cstdint>

#define D 64
#define MAXN 100000
#define MAXE 1600000
#define CAP 64        // padded adjacency capacity per node (Poisson(16): safe)

// Scratch (device globals — PLAIN loads/stores only; atomics on module
// globals trap with cudaErrorInvalidAddressSpace in this environment).
__device__ __align__(16) float g_hn[(size_t)MAXN * D];   // neighbor mean
__device__ __align__(16) float g_h1[(size_t)MAXN * D];   // layer-1 output
__device__ int g_adj[(size_t)MAXN * CAP];  // padded adjacency (src lists)
__device__ int g_is64;                     // 1 if index buffers are int64

// Atomics only on d_out scratch (harness-allocated):
//   scratch[0..N) = per-node degree counters (cur). gemm2 overwrites later.

__device__ __forceinline__ int load_idx(const void* p, int e, int N) {
    int v = g_is64 ? (int)((const long long*)p)[e] : ((const int*)p)[e];
    return v < 0 ? 0 : (v >= N ? N - 1 : v);
}

// ---- f32x2 packed math (FFMA2: 2 fp32 FMAs per FMA-pipe slot) ----
__device__ __forceinline__ unsigned long long pack2(float lo, float hi) {
    unsigned long long r;
    asm("mov.b64 %0, {%1, %2};"
        : "=l"(r) : "r"(__float_as_uint(lo)), "r"(__float_as_uint(hi)));
    return r;
}
__device__ __forceinline__ void fma2(unsigned long long& d,
                                     unsigned long long a,
                                     unsigned long long b) {
    asm("fma.rn.f32x2 %0, %1, %2, %0;" : "+l"(d) : "l"(a), "l"(b));
}
__device__ __forceinline__ void add2(unsigned long long& d,
                                     unsigned long long b) {
    asm("add.rn.f32x2 %0, %0, %1;" : "+l"(d) : "l"(b));
}

// ---------------------------------------------------------------------------
// Fused probe + counter zero. Block 0: dtype probe (int64 indices < 2^31
// have all odd 32-bit words zero); blocks 1..: zero the degree counters.
// ---------------------------------------------------------------------------
__global__ void probe_zero_kernel(const unsigned* __restrict__ raw, int E,
                                  int* __restrict__ cur, int N) {
    if (blockIdx.x == 0) {
        __shared__ int s[256];
        int t = threadIdx.x;
        int nprobe = E < 4096 ? E : 4096;
        int any = 0;
        for (int i = t; i < nprobe; i += 256) any |= (int)raw[2 * i + 1];
        s[t] = any;
        __syncthreads();
        #pragma unroll
        for (int off = 128; off > 0; off >>= 1) {
            if (t < off) s[t] |= s[t + off];
            __syncthreads();
        }
        if (t == 0) g_is64 = (s[0] == 0) ? 1 : 0;
    } else {
        int i = (blockIdx.x - 1) * blockDim.x + threadIdx.x;
        if (i < N) cur[i] = 0;
    }
}

// ---------------------------------------------------------------------------
// Single-pass padded adjacency build: one int atomic + one 4B store per edge.
// ---------------------------------------------------------------------------
__global__ void fill_adj_kernel(const void* __restrict__ srcp,
                                const void* __restrict__ dstp,
                                int* __restrict__ cur, int E, int N) {
    int e = blockIdx.x * blockDim.x + threadIdx.x;
    if (e < E) {
        int d = load_idx(dstp, e, N);
        int pos = atomicAdd(&cur[d], 1);
        if (pos < CAP)
            g_adj[(size_t)d * CAP + pos] = load_idx(srcp, e, N);
    }
}

// ---------------------------------------------------------------------------
// Gather-mean: 16 threads per node, each owns one float4 chunk; contiguous
// walk over the node's padded adjacency slice, 4x unroll for MLP.
// ---------------------------------------------------------------------------
__global__ void gather_kernel(const float* __restrict__ x,
                              const int* __restrict__ cur, int N, int use_h1) {
    const float* h = use_h1 ? (const float*)g_h1 : x;
    int gid = blockIdx.x * blockDim.x + threadIdx.x;
    int n = gid >> 4;
    if (n >= N) return;
    int c = (gid & 15) << 2;

    int deg = cur[n];
    int cnt = deg < CAP ? deg : CAP;
    const int* adj = g_adj + (size_t)n * CAP;

    float ax = 0.0f, ay = 0.0f, az = 0.0f, aw = 0.0f;
    int j = 0;
    for (; j + 3 < cnt; j += 4) {
        int s0 = adj[j],     s1 = adj[j + 1];
        int s2 = adj[j + 2], s3 = adj[j + 3];
        float4 v0 = *reinterpret_cast<const float4*>(h + ((size_t)s0 << 6) + c);
        float4 v1 = *reinterpret_cast<const float4*>(h + ((size_t)s1 << 6) + c);
        float4 v2 = *reinterpret_cast<const float4*>(h + ((size_t)s2 << 6) + c);
        float4 v3 = *reinterpret_cast<const float4*>(h + ((size_t)s3 << 6) + c);
        ax += (v0.x + v1.x) + (v2.x + v3.x);
        ay += (v0.y + v1.y) + (v2.y + v3.y);
        az += (v0.z + v1.z) + (v2.z + v3.z);
        aw += (v0.w + v1.w) + (v2.w + v3.w);
    }
    for (; j < cnt; j++) {
        int s0 = adj[j];
        float4 v0 = *reinterpret_cast<const float4*>(h + ((size_t)s0 << 6) + c);
        ax += v0.x; ay += v0.y; az += v0.z; aw += v0.w;
    }
    float inv = 1.0f / fmaxf((float)deg, 1.0f);
    float4 r;
    r.x = ax * inv; r.y = ay * inv; r.z = az * inv; r.w = aw * inv;
    *reinterpret_cast<float4*>(g_hn + ((size_t)n << 6) + c) = r;
}

// ---------------------------------------------------------------------------
// GEMM v4 (FFMA2, high intensity): 256-row x 64-col tile, 256 threads,
// 8 rows x 8 cols per thread. Per 4-k chunk: 32 LDS.128 vs 256 FFMA2
// (0.125 LDS/FFMA2, half of v3) -> crossbar and FMA pipe co-balanced.
// smem: sWs|sWn (32KB) + sx|sh (128KB) = 160KB, 1 block/SM.
// ---------------------------------------------------------------------------
__global__ void gemm_kernel(const float* __restrict__ x,
                            const float* __restrict__ Ws,
                            const float* __restrict__ Wn,
                            const float* __restrict__ b,
                            float* __restrict__ o,
                            int N, int ntiles, int use_h1, int out_is_h1) {
    const float* in = use_h1 ? (const float*)g_h1 : x;
    float* out      = out_is_h1 ? (float*)g_h1 : o;

    extern __shared__ float sm[];
    float* sWs = sm;               // [64][64]   16KB
    float* sWn = sm + 4096;        // [64][64]   16KB
    float* sx  = sm + 8192;        // [256][64]  64KB
    float* sh  = sm + 8192 + 16384; // [256][64] 64KB

    const int t = threadIdx.x;

    // Stage both weight matrices once per block (float4)
    for (int i = t; i < 1024; i += 256) {
        reinterpret_cast<float4*>(sWs)[i] =
            reinterpret_cast<const float4*>(Ws)[i];
        reinterpret_cast<float4*>(sWn)[i] =
            reinterpret_cast<const float4*>(Wn)[i];
    }

    const int cg = (t & 7) << 3;    // 8 consecutive cols
    const int rg = (t >> 3) << 3;   // 8 rows
    const unsigned long long bias_p[4] = {
        pack2(b[cg + 0], b[cg + 1]), pack2(b[cg + 2], b[cg + 3]),
        pack2(b[cg + 4], b[cg + 5]), pack2(b[cg + 6], b[cg + 7])
    };

    for (int tile = blockIdx.x; tile < ntiles; tile += gridDim.x) {
        int base = tile * 256;
        __syncthreads();

        // Stage 256 rows of in and hn (float4 over k): 16 float4-rows/thread
        for (int i = t; i < 4096; i += 256) {
            int rr = i >> 4;            // 0..255
            int kk4 = (i & 15);         // float4 index within row
            int row = base + rr;
            float4 vx = make_float4(0.f, 0.f, 0.f, 0.f);
            float4 vh = vx;
            if (row < N) {
                vx = reinterpret_cast<const float4*>(in + ((size_t)row << 6))[kk4];
                vh = reinterpret_cast<const float4*>(g_hn + ((size_t)row << 6))[kk4];
            }
            reinterpret_cast<float4*>(sx + rr * 64)[kk4] = vx;
            reinterpret_cast<float4*>(sh + rr * 64)[kk4] = vh;
        }
        __syncthreads();

        unsigned long long acc[8][4];
        #pragma unroll
        for (int r = 0; r < 8; r++)
            #pragma unroll
            for (int c = 0; c < 4; c++) acc[r][c] = 0ull;

        for (int k0 = 0; k0 < 64; k0 += 4) {
            float4 xv[8], hv[8];
            #pragma unroll
            for (int r = 0; r < 8; r++) {
                xv[r] = *reinterpret_cast<const float4*>(sx + (rg + r) * 64 + k0);
                hv[r] = *reinterpret_cast<const float4*>(sh + (rg + r) * 64 + k0);
            }
            #pragma unroll
            for (int kk = 0; kk < 4; kk++) {
                ulonglong2 ws0 = *reinterpret_cast<const ulonglong2*>(
                    sWs + (k0 + kk) * 64 + cg);
                ulonglong2 ws1 = *reinterpret_cast<const ulonglong2*>(
                    sWs + (k0 + kk) * 64 + cg + 4);
                ulonglong2 wn0 = *reinterpret_cast<const ulonglong2*>(
                    sWn + (k0 + kk) * 64 + cg);
                ulonglong2 wn1 = *reinterpret_cast<const ulonglong2*>(
                    sWn + (k0 + kk) * 64 + cg + 4);
                #pragma unroll
                for (int r = 0; r < 8; r++) {
                    float vx = reinterpret_cast<const float*>(&xv[r])[kk];
                    float vh = reinterpret_cast<const float*>(&hv[r])[kk];
                    unsigned long long vx2 = pack2(vx, vx);
                    unsigned long long vh2 = pack2(vh, vh);
                    fma2(acc[r][0], vx2, ws0.x);
                    fma2(acc[r][1], vx2, ws0.y);
                    fma2(acc[r][2], vx2, ws1.x);
                    fma2(acc[r][3], vx2, ws1.y);
                    fma2(acc[r][0], vh2, wn0.x);
                    fma2(acc[r][1], vh2, wn0.y);
                    fma2(acc[r][2], vh2, wn1.x);
                    fma2(acc[r][3], vh2, wn1.y);
                }
            }
        }

        #pragma unroll
        for (int r = 0; r < 8; r++) {
            int row = base + rg + r;
            if (row < N) {
                add2(acc[r][0], bias_p[0]);
                add2(acc[r][1], bias_p[1]);
                add2(acc[r][2], bias_p[2]);
                add2(acc[r][3], bias_p[3]);
                ulonglong2 v0, v1;
                v0.x = acc[r][0]; v0.y = acc[r][1];
                v1.x = acc[r][2]; v1.y = acc[r][3];
                *reinterpret_cast<ulonglong2*>(out + ((size_t)row << 6) + cg) = v0;
                *reinterpret_cast<ulonglong2*>(out + ((size_t)row << 6) + cg + 4) = v1;
            }
        }
    }
}

// ---------------------------------------------------------------------------
// Launch: probe/zero + adjacency build + 2 SAGE layers. 6 kernels total.
// Inputs: x, src, dst, W_self1, W_neigh1, b1, W_self2, W_neigh2, b2
// ---------------------------------------------------------------------------
extern "C" void kernel_launch(void* const* d_in, const int* in_sizes, int n_in,
                              void* d_out, int out_size) {
    const float* x   = (const float*)d_in[0];
    const void*  src = d_in[1];
    const void*  dst = d_in[2];
    const float* Ws1 = (const float*)d_in[3];
    const float* Wn1 = (const float*)d_in[4];
    const float* b1  = (const float*)d_in[5];
    const float* Ws2 = (const float*)d_in[6];
    const float* Wn2 = (const float*)d_in[7];
    const float* b2  = (const float*)d_in[8];
    float* out = (float*)d_out;

    int N = in_sizes[0] / D;
    int E = in_sizes[1];

    int* cur = (int*)d_out;   // degree counters in harness-allocated memory

    const int TPB = 256;
    int ngrid = (N + TPB - 1) / TPB;
    int egrid = (E + TPB - 1) / TPB;
    int ggrid = ((N * 16) + TPB - 1) / TPB;   // gather: 16 threads/node
    int ntiles = (N + 255) / 256;             // 256-row tiles
    int mgrid = ntiles < 296 ? ntiles : 296;

    const int GEMM_SMEM = 160 * 1024;   // 32KB weights + 128KB rows
    cudaFuncSetAttribute(gemm_kernel,
                         cudaFuncAttributeMaxDynamicSharedMemorySize, GEMM_SMEM);

    // ---- Probe + zero counters, then single-pass adjacency build ----
    probe_zero_kernel<<<ngrid + 1, TPB>>>((const unsigned*)dst, E, cur, N);
    fill_adj_kernel<<<egrid, TPB>>>(src, dst, cur, E, N);

    // ---- Layer 1 ----
    gather_kernel<<<ggrid, TPB>>>(x, cur, N, /*use_h1=*/0);
    gemm_kernel<<<mgrid, TPB, GEMM_SMEM>>>(x, Ws1, Wn1, b1, out, N, ntiles,
                                           /*use_h1=*/0, /*out_is_h1=*/1);

    // ---- Layer 2 ----
    gather_kernel<<<ggrid, TPB>>>(x, cur, N, /*use_h1=*/1);
    gemm_kernel<<<mgrid, TPB, GEMM_SMEM>>>(x, Ws2, Wn2, b2, out, N, ntiles,
                                           /*use_h1=*/1, /*out_is_h1=*/0);
}

// round 14
// speedup vs baseline: 1.0196x; 1.0196x over previous
#include <cuda_runtime.h>
#include <cstdint>

#define D 64
#define MAXN 100000
#define MAXE 1600000
#define CAP 64        // padded adjacency capacity per node (Poisson(16): safe)

// Scratch (device globals — PLAIN loads/stores only; atomics on module
// globals trap with cudaErrorInvalidAddressSpace in this environment).
__device__ __align__(16) float g_hn[(size_t)MAXN * D];   // neighbor mean
__device__ __align__(16) float g_h1[(size_t)MAXN * D];   // layer-1 output
__device__ int g_adj[(size_t)MAXN * CAP];  // padded adjacency (src lists)
__device__ int g_is64;                     // 1 if index buffers are int64

// Atomics only on d_out scratch (harness-allocated):
//   scratch[0..N) = per-node degree counters (cur). gemm2 overwrites later.

__device__ __forceinline__ int load_idx(const void* p, int e, int N) {
    int v = g_is64 ? (int)((const long long*)p)[e] : ((const int*)p)[e];
    return v < 0 ? 0 : (v >= N ? N - 1 : v);
}

// ---- f32x2 packed math (FFMA2: 2 fp32 FMAs per FMA-pipe slot) ----
__device__ __forceinline__ unsigned long long pack2(float lo, float hi) {
    unsigned long long r;
    asm("mov.b64 %0, {%1, %2};"
        : "=l"(r) : "r"(__float_as_uint(lo)), "r"(__float_as_uint(hi)));
    return r;
}
__device__ __forceinline__ void fma2(unsigned long long& d,
                                     unsigned long long a,
                                     unsigned long long b) {
    asm("fma.rn.f32x2 %0, %1, %2, %0;" : "+l"(d) : "l"(a), "l"(b));
}
__device__ __forceinline__ void add2(unsigned long long& d,
                                     unsigned long long b) {
    asm("add.rn.f32x2 %0, %0, %1;" : "+l"(d) : "l"(b));
}

// ---------------------------------------------------------------------------
// Fused probe + counter zero. Block 0: dtype probe (int64 indices < 2^31
// have all odd 32-bit words zero); blocks 1..: zero the degree counters.
// ---------------------------------------------------------------------------
__global__ void probe_zero_kernel(const unsigned* __restrict__ raw, int E,
                                  int* __restrict__ cur, int N) {
    if (blockIdx.x == 0) {
        __shared__ int s[256];
        int t = threadIdx.x;
        int nprobe = E < 4096 ? E : 4096;
        int any = 0;
        for (int i = t; i < nprobe; i += 256) any |= (int)raw[2 * i + 1];
        s[t] = any;
        __syncthreads();
        #pragma unroll
        for (int off = 128; off > 0; off >>= 1) {
            if (t < off) s[t] |= s[t + off];
            __syncthreads();
        }
        if (t == 0) g_is64 = (s[0] == 0) ? 1 : 0;
    } else {
        int i = (blockIdx.x - 1) * blockDim.x + threadIdx.x;
        if (i < N) cur[i] = 0;
    }
}

// ---------------------------------------------------------------------------
// Single-pass padded adjacency build: one int atomic + one 4B store per edge.
// ---------------------------------------------------------------------------
__global__ void fill_adj_kernel(const void* __restrict__ srcp,
                                const void* __restrict__ dstp,
                                int* __restrict__ cur, int E, int N) {
    int e = blockIdx.x * blockDim.x + threadIdx.x;
    if (e < E) {
        int d = load_idx(dstp, e, N);
        int pos = atomicAdd(&cur[d], 1);
        if (pos < CAP)
            g_adj[(size_t)d * CAP + pos] = load_idx(srcp, e, N);
    }
}

// ---------------------------------------------------------------------------
// Gather-mean: 16 threads per node, each owns one float4 chunk; contiguous
// walk over the node's padded adjacency slice, 4x unroll for MLP.
// ---------------------------------------------------------------------------
__global__ void gather_kernel(const float* __restrict__ x,
                              const int* __restrict__ cur, int N, int use_h1) {
    const float* h = use_h1 ? (const float*)g_h1 : x;
    int gid = blockIdx.x * blockDim.x + threadIdx.x;
    int n = gid >> 4;
    if (n >= N) return;
    int c = (gid & 15) << 2;

    int deg = cur[n];
    int cnt = deg < CAP ? deg : CAP;
    const int* adj = g_adj + (size_t)n * CAP;

    float ax = 0.0f, ay = 0.0f, az = 0.0f, aw = 0.0f;
    int j = 0;
    for (; j + 3 < cnt; j += 4) {
        int s0 = adj[j],     s1 = adj[j + 1];
        int s2 = adj[j + 2], s3 = adj[j + 3];
        float4 v0 = *reinterpret_cast<const float4*>(h + ((size_t)s0 << 6) + c);
        float4 v1 = *reinterpret_cast<const float4*>(h + ((size_t)s1 << 6) + c);
        float4 v2 = *reinterpret_cast<const float4*>(h + ((size_t)s2 << 6) + c);
        float4 v3 = *reinterpret_cast<const float4*>(h + ((size_t)s3 << 6) + c);
        ax += (v0.x + v1.x) + (v2.x + v3.x);
        ay += (v0.y + v1.y) + (v2.y + v3.y);
        az += (v0.z + v1.z) + (v2.z + v3.z);
        aw += (v0.w + v1.w) + (v2.w + v3.w);
    }
    for (; j < cnt; j++) {
        int s0 = adj[j];
        float4 v0 = *reinterpret_cast<const float4*>(h + ((size_t)s0 << 6) + c);
        ax += v0.x; ay += v0.y; az += v0.z; aw += v0.w;
    }
    float inv = 1.0f / fmaxf((float)deg, 1.0f);
    float4 r;
    r.x = ax * inv; r.y = ay * inv; r.z = az * inv; r.w = aw * inv;
    *reinterpret_cast<float4*>(g_hn + ((size_t)n << 6) + c) = r;
}

// ---------------------------------------------------------------------------
// GEMM v5 (FFMA2, balanced + occupancy): 128-row x 64-col tile, 128 threads,
// 8 rows x 8 cols per thread. Per 4-k chunk: 32 LDS.128 vs 256 FFMA2
// (crossbar time == FMA time). smem = 32KB weights + 64KB rows = 96KB ->
// 2 blocks/SM for latency hiding; k-loop unroll 2 interleaves LDS w/ FFMA2.
// ---------------------------------------------------------------------------
__global__ void gemm_kernel(const float* __restrict__ x,
                            const float* __restrict__ Ws,
                            const float* __restrict__ Wn,
                            const float* __restrict__ b,
                            float* __restrict__ o,
                            int N, int ntiles, int use_h1, int out_is_h1) {
    const float* in = use_h1 ? (const float*)g_h1 : x;
    float* out      = out_is_h1 ? (float*)g_h1 : o;

    extern __shared__ float sm[];
    float* sWs = sm;                 // [64][64]   16KB
    float* sWn = sm + 4096;          // [64][64]   16KB
    float* sx  = sm + 8192;          // [128][64]  32KB
    float* sh  = sm + 8192 + 8192;   // [128][64]  32KB

    const int t = threadIdx.x;       // 0..127

    // Stage both weight matrices once per block (float4)
    for (int i = t; i < 1024; i += 128) {
        reinterpret_cast<float4*>(sWs)[i] =
            reinterpret_cast<const float4*>(Ws)[i];
        reinterpret_cast<float4*>(sWn)[i] =
            reinterpret_cast<const float4*>(Wn)[i];
    }

    const int cg = (t & 7) << 3;    // 8 consecutive cols
    const int rg = (t >> 3) << 3;   // 8 rows
    const unsigned long long bias_p[4] = {
        pack2(b[cg + 0], b[cg + 1]), pack2(b[cg + 2], b[cg + 3]),
        pack2(b[cg + 4], b[cg + 5]), pack2(b[cg + 6], b[cg + 7])
    };

    for (int tile = blockIdx.x; tile < ntiles; tile += gridDim.x) {
        int base = tile * 128;
        __syncthreads();

        // Stage 128 rows of in and hn (float4 over k): 16 float4/thread/array
        for (int i = t; i < 2048; i += 128) {
            int rr = i >> 4;            // 0..127
            int kk4 = (i & 15);         // float4 index within row
            int row = base + rr;
            float4 vx = make_float4(0.f, 0.f, 0.f, 0.f);
            float4 vh = vx;
            if (row < N) {
                vx = reinterpret_cast<const float4*>(in + ((size_t)row << 6))[kk4];
                vh = reinterpret_cast<const float4*>(g_hn + ((size_t)row << 6))[kk4];
            }
            reinterpret_cast<float4*>(sx + rr * 64)[kk4] = vx;
            reinterpret_cast<float4*>(sh + rr * 64)[kk4] = vh;
        }
        __syncthreads();

        unsigned long long acc[8][4];
        #pragma unroll
        for (int r = 0; r < 8; r++)
            #pragma unroll
            for (int c = 0; c < 4; c++) acc[r][c] = 0ull;

        #pragma unroll 2
        for (int k0 = 0; k0 < 64; k0 += 4) {
            float4 xv[8], hv[8];
            #pragma unroll
            for (int r = 0; r < 8; r++) {
                xv[r] = *reinterpret_cast<const float4*>(sx + (rg + r) * 64 + k0);
                hv[r] = *reinterpret_cast<const float4*>(sh + (rg + r) * 64 + k0);
            }
            #pragma unroll
            for (int kk = 0; kk < 4; kk++) {
                ulonglong2 ws0 = *reinterpret_cast<const ulonglong2*>(
                    sWs + (k0 + kk) * 64 + cg);
                ulonglong2 ws1 = *reinterpret_cast<const ulonglong2*>(
                    sWs + (k0 + kk) * 64 + cg + 4);
                ulonglong2 wn0 = *reinterpret_cast<const ulonglong2*>(
                    sWn + (k0 + kk) * 64 + cg);
                ulonglong2 wn1 = *reinterpret_cast<const ulonglong2*>(
                    sWn + (k0 + kk) * 64 + cg + 4);
                #pragma unroll
                for (int r = 0; r < 8; r++) {
                    float vx = reinterpret_cast<const float*>(&xv[r])[kk];
                    float vh = reinterpret_cast<const float*>(&hv[r])[kk];
                    unsigned long long vx2 = pack2(vx, vx);
                    unsigned long long vh2 = pack2(vh, vh);
                    fma2(acc[r][0], vx2, ws0.x);
                    fma2(acc[r][1], vx2, ws0.y);
                    fma2(acc[r][2], vx2, ws1.x);
                    fma2(acc[r][3], vx2, ws1.y);
                    fma2(acc[r][0], vh2, wn0.x);
                    fma2(acc[r][1], vh2, wn0.y);
                    fma2(acc[r][2], vh2, wn1.x);
                    fma2(acc[r][3], vh2, wn1.y);
                }
            }
        }

        #pragma unroll
        for (int r = 0; r < 8; r++) {
            int row = base + rg + r;
            if (row < N) {
                add2(acc[r][0], bias_p[0]);
                add2(acc[r][1], bias_p[1]);
                add2(acc[r][2], bias_p[2]);
                add2(acc[r][3], bias_p[3]);
                ulonglong2 v0, v1;
                v0.x = acc[r][0]; v0.y = acc[r][1];
                v1.x = acc[r][2]; v1.y = acc[r][3];
                *reinterpret_cast<ulonglong2*>(out + ((size_t)row << 6) + cg) = v0;
                *reinterpret_cast<ulonglong2*>(out + ((size_t)row << 6) + cg + 4) = v1;
            }
        }
    }
}

// ---------------------------------------------------------------------------
// Launch: probe/zero + adjacency build + 2 SAGE layers. 6 kernels total.
// Inputs: x, src, dst, W_self1, W_neigh1, b1, W_self2, W_neigh2, b2
// ---------------------------------------------------------------------------
extern "C" void kernel_launch(void* const* d_in, const int* in_sizes, int n_in,
                              void* d_out, int out_size) {
    const float* x   = (const float*)d_in[0];
    const void*  src = d_in[1];
    const void*  dst = d_in[2];
    const float* Ws1 = (const float*)d_in[3];
    const float* Wn1 = (const float*)d_in[4];
    const float* b1  = (const float*)d_in[5];
    const float* Ws2 = (const float*)d_in[6];
    const float* Wn2 = (const float*)d_in[7];
    const float* b2  = (const float*)d_in[8];
    float* out = (float*)d_out;

    int N = in_sizes[0] / D;
    int E = in_sizes[1];

    int* cur = (int*)d_out;   // degree counters in harness-allocated memory

    const int TPB = 256;
    int ngrid = (N + TPB - 1) / TPB;
    int egrid = (E + TPB - 1) / TPB;
    int ggrid = ((N * 16) + TPB - 1) / TPB;   // gather: 16 threads/node
    int ntiles = (N + 127) / 128;             // 128-row tiles
    int mgrid = ntiles < 296 ? ntiles : 296;  // 2 blocks/SM persistent

    const int GEMM_SMEM = 96 * 1024;   // 32KB weights + 64KB rows
    cudaFuncSetAttribute(gemm_kernel,
                         cudaFuncAttributeMaxDynamicSharedMemorySize, GEMM_SMEM);

    // ---- Probe + zero counters, then single-pass adjacency build ----
    probe_zero_kernel<<<ngrid + 1, TPB>>>((const unsigned*)dst, E, cur, N);
    fill_adj_kernel<<<egrid, TPB>>>(src, dst, cur, E, N);

    // ---- Layer 1 ----
    gather_kernel<<<ggrid, TPB>>>(x, cur, N, /*use_h1=*/0);
    gemm_kernel<<<mgrid, 128, GEMM_SMEM>>>(x, Ws1, Wn1, b1, out, N, ntiles,
                                           /*use_h1=*/0, /*out_is_h1=*/1);

    // ---- Layer 2 ----
    gather_kernel<<<ggrid, TPB>>>(x, cur, N, /*use_h1=*/1);
    gemm_kernel<<<mgrid, 128, GEMM_SMEM>>>(x, Ws2, Wn2, b2, out, N, ntiles,
                                           /*use_h1=*/1, /*out_is_h1=*/0);
}

// round 15
// speedup vs baseline: 1.0536x; 1.0334x over previous
#include <cuda_runtime.h>
#include <cstdint>

#define D 64
#define MAXN 100000
#define MAXE 1600000
#define CAP 64        // padded adjacency capacity per node (Poisson(16): safe)

// Scratch (device globals — PLAIN loads/stores only; atomics on module
// globals trap with cudaErrorInvalidAddressSpace in this environment).
__device__ __align__(16) float g_hn[(size_t)MAXN * D];   // neighbor mean
__device__ __align__(16) float g_h1[(size_t)MAXN * D];   // layer-1 output
__device__ int g_adj[(size_t)MAXN * CAP];  // padded adjacency (src lists)
__device__ int g_is64;                     // 1 if index buffers are int64

// Atomics only on d_out scratch (harness-allocated):
//   scratch[0..N) = per-node degree counters (cur). gemm2 overwrites later.

__device__ __forceinline__ int load_idx(const void* p, int e, int N) {
    int v = g_is64 ? (int)((const long long*)p)[e] : ((const int*)p)[e];
    return v < 0 ? 0 : (v >= N ? N - 1 : v);
}

// ---- f32x2 packed math (FFMA2: 2 fp32 FMAs per FMA-pipe slot) ----
__device__ __forceinline__ unsigned long long pack2(float lo, float hi) {
    unsigned long long r;
    asm("mov.b64 %0, {%1, %2};"
        : "=l"(r) : "r"(__float_as_uint(lo)), "r"(__float_as_uint(hi)));
    return r;
}
__device__ __forceinline__ void fma2(unsigned long long& d,
                                     unsigned long long a,
                                     unsigned long long b) {
    asm("fma.rn.f32x2 %0, %1, %2, %0;" : "+l"(d) : "l"(a), "l"(b));
}
__device__ __forceinline__ void add2(unsigned long long& d,
                                     unsigned long long b) {
    asm("add.rn.f32x2 %0, %0, %1;" : "+l"(d) : "l"(b));
}

// ---------------------------------------------------------------------------
// Fused probe + counter zero. Block 0: dtype probe (int64 indices < 2^31
// have all odd 32-bit words zero); blocks 1..: zero the degree counters.
// ---------------------------------------------------------------------------
__global__ void probe_zero_kernel(const unsigned* __restrict__ raw, int E,
                                  int* __restrict__ cur, int N) {
    if (blockIdx.x == 0) {
        __shared__ int s[256];
        int t = threadIdx.x;
        int nprobe = E < 4096 ? E : 4096;
        int any = 0;
        for (int i = t; i < nprobe; i += 256) any |= (int)raw[2 * i + 1];
        s[t] = any;
        __syncthreads();
        #pragma unroll
        for (int off = 128; off > 0; off >>= 1) {
            if (t < off) s[t] |= s[t + off];
            __syncthreads();
        }
        if (t == 0) g_is64 = (s[0] == 0) ? 1 : 0;
    } else {
        int i = (blockIdx.x - 1) * blockDim.x + threadIdx.x;
        if (i < N) cur[i] = 0;
    }
}

// ---------------------------------------------------------------------------
// Single-pass padded adjacency build: one int atomic + one 4B store per edge.
// ---------------------------------------------------------------------------
__global__ void fill_adj_kernel(const void* __restrict__ srcp,
                                const void* __restrict__ dstp,
                                int* __restrict__ cur, int E, int N) {
    int e = blockIdx.x * blockDim.x + threadIdx.x;
    if (e < E) {
        int d = load_idx(dstp, e, N);
        int pos = atomicAdd(&cur[d], 1);
        if (pos < CAP)
            g_adj[(size_t)d * CAP + pos] = load_idx(srcp, e, N);
    }
}

// ---------------------------------------------------------------------------
// Gather-mean: 16 threads per node, each owns one float4 chunk; contiguous
// walk over the node's padded adjacency slice, 4x unroll for MLP.
// ---------------------------------------------------------------------------
__global__ void gather_kernel(const float* __restrict__ x,
                              const int* __restrict__ cur, int N, int use_h1) {
    const float* h = use_h1 ? (const float*)g_h1 : x;
    int gid = blockIdx.x * blockDim.x + threadIdx.x;
    int n = gid >> 4;
    if (n >= N) return;
    int c = (gid & 15) << 2;

    int deg = cur[n];
    int cnt = deg < CAP ? deg : CAP;
    const int* adj = g_adj + (size_t)n * CAP;

    float ax = 0.0f, ay = 0.0f, az = 0.0f, aw = 0.0f;
    int j = 0;
    for (; j + 3 < cnt; j += 4) {
        int s0 = adj[j],     s1 = adj[j + 1];
        int s2 = adj[j + 2], s3 = adj[j + 3];
        float4 v0 = *reinterpret_cast<const float4*>(h + ((size_t)s0 << 6) + c);
        float4 v1 = *reinterpret_cast<const float4*>(h + ((size_t)s1 << 6) + c);
        float4 v2 = *reinterpret_cast<const float4*>(h + ((size_t)s2 << 6) + c);
        float4 v3 = *reinterpret_cast<const float4*>(h + ((size_t)s3 << 6) + c);
        ax += (v0.x + v1.x) + (v2.x + v3.x);
        ay += (v0.y + v1.y) + (v2.y + v3.y);
        az += (v0.z + v1.z) + (v2.z + v3.z);
        aw += (v0.w + v1.w) + (v2.w + v3.w);
    }
    for (; j < cnt; j++) {
        int s0 = adj[j];
        float4 v0 = *reinterpret_cast<const float4*>(h + ((size_t)s0 << 6) + c);
        ax += v0.x; ay += v0.y; az += v0.z; aw += v0.w;
    }
    float inv = 1.0f / fmaxf((float)deg, 1.0f);
    float4 r;
    r.x = ax * inv; r.y = ay * inv; r.z = az * inv; r.w = aw * inv;
    *reinterpret_cast<float4*>(g_hn + ((size_t)n << 6) + c) = r;
}

// ---------------------------------------------------------------------------
// GEMM v6 (FFMA2, conflict-free 4x8): 128-row x 64-col tile, 256 threads.
// Thread owns 4 rows x 8 cols, the 8 cols as TWO separated float4 groups
// (cols 4*(t&7)..+3 and 32+4*(t&7)..+3) so every weight LDS.128 phase is
// 128B-contiguous (no bank conflicts). Per 4k-chunk: 24 LDS.128 vs 128
// FFMA2. smem = 32KB weights + 64KB rows = 96KB -> 2 blocks/SM, 16 warps.
// ---------------------------------------------------------------------------
__global__ void gemm_kernel(const float* __restrict__ x,
                            const float* __restrict__ Ws,
                            const float* __restrict__ Wn,
                            const float* __restrict__ b,
                            float* __restrict__ o,
                            int N, int ntiles, int use_h1, int out_is_h1) {
    const float* in = use_h1 ? (const float*)g_h1 : x;
    float* out      = out_is_h1 ? (float*)g_h1 : o;

    extern __shared__ float sm[];
    float* sWs = sm;                 // [64][64]   16KB
    float* sWn = sm + 4096;          // [64][64]   16KB
    float* sx  = sm + 8192;          // [128][64]  32KB
    float* sh  = sm + 8192 + 8192;   // [128][64]  32KB

    const int t = threadIdx.x;       // 0..255

    // Stage both weight matrices once per block (float4)
    for (int i = t; i < 1024; i += 256) {
        reinterpret_cast<float4*>(sWs)[i] =
            reinterpret_cast<const float4*>(Ws)[i];
        reinterpret_cast<float4*>(sWn)[i] =
            reinterpret_cast<const float4*>(Wn)[i];
    }

    const int cg = (t & 7) << 2;    // first col group: cols cg..cg+3
    //                                 second col group: cols cg+32..cg+35
    const int rg = (t >> 3) << 2;   // 4 rows: rg..rg+3
    const unsigned long long bias_p[4] = {
        pack2(b[cg + 0],  b[cg + 1]),  pack2(b[cg + 2],  b[cg + 3]),
        pack2(b[cg + 32], b[cg + 33]), pack2(b[cg + 34], b[cg + 35])
    };

    for (int tile = blockIdx.x; tile < ntiles; tile += gridDim.x) {
        int base = tile * 128;
        __syncthreads();

        // Stage 128 rows of in and hn (float4 over k): 8 float4/thread/array
        for (int i = t; i < 2048; i += 256) {
            int rr = i >> 4;            // 0..127
            int kk4 = (i & 15);         // float4 index within row
            int row = base + rr;
            float4 vx = make_float4(0.f, 0.f, 0.f, 0.f);
            float4 vh = vx;
            if (row < N) {
                vx = reinterpret_cast<const float4*>(in + ((size_t)row << 6))[kk4];
                vh = reinterpret_cast<const float4*>(g_hn + ((size_t)row << 6))[kk4];
            }
            reinterpret_cast<float4*>(sx + rr * 64)[kk4] = vx;
            reinterpret_cast<float4*>(sh + rr * 64)[kk4] = vh;
        }
        __syncthreads();

        // acc[r][0..1] = cols cg..cg+3 ; acc[r][2..3] = cols cg+32..cg+35
        unsigned long long acc[4][4];
        #pragma unroll
        for (int r = 0; r < 4; r++)
            #pragma unroll
            for (int c = 0; c < 4; c++) acc[r][c] = 0ull;

        #pragma unroll 2
        for (int k0 = 0; k0 < 64; k0 += 4) {
            float4 xv[4], hv[4];
            #pragma unroll
            for (int r = 0; r < 4; r++) {
                xv[r] = *reinterpret_cast<const float4*>(sx + (rg + r) * 64 + k0);
                hv[r] = *reinterpret_cast<const float4*>(sh + (rg + r) * 64 + k0);
            }
            #pragma unroll
            for (int kk = 0; kk < 4; kk++) {
                const float* wsrow = sWs + (k0 + kk) * 64;
                const float* wnrow = sWn + (k0 + kk) * 64;
                ulonglong2 ws0 = *reinterpret_cast<const ulonglong2*>(wsrow + cg);
                ulonglong2 ws1 = *reinterpret_cast<const ulonglong2*>(wsrow + cg + 32);
                ulonglong2 wn0 = *reinterpret_cast<const ulonglong2*>(wnrow + cg);
                ulonglong2 wn1 = *reinterpret_cast<const ulonglong2*>(wnrow + cg + 32);
                #pragma unroll
                for (int r = 0; r < 4; r++) {
                    float vx = reinterpret_cast<const float*>(&xv[r])[kk];
                    float vh = reinterpret_cast<const float*>(&hv[r])[kk];
                    unsigned long long vx2 = pack2(vx, vx);
                    unsigned long long vh2 = pack2(vh, vh);
                    fma2(acc[r][0], vx2, ws0.x);
                    fma2(acc[r][1], vx2, ws0.y);
                    fma2(acc[r][2], vx2, ws1.x);
                    fma2(acc[r][3], vx2, ws1.y);
                    fma2(acc[r][0], vh2, wn0.x);
                    fma2(acc[r][1], vh2, wn0.y);
                    fma2(acc[r][2], vh2, wn1.x);
                    fma2(acc[r][3], vh2, wn1.y);
                }
            }
        }

        #pragma unroll
        for (int r = 0; r < 4; r++) {
            int row = base + rg + r;
            if (row < N) {
                add2(acc[r][0], bias_p[0]);
                add2(acc[r][1], bias_p[1]);
                add2(acc[r][2], bias_p[2]);
                add2(acc[r][3], bias_p[3]);
                ulonglong2 v0, v1;
                v0.x = acc[r][0]; v0.y = acc[r][1];
                v1.x = acc[r][2]; v1.y = acc[r][3];
                *reinterpret_cast<ulonglong2*>(out + ((size_t)row << 6) + cg) = v0;
                *reinterpret_cast<ulonglong2*>(out + ((size_t)row << 6) + cg + 32) = v1;
            }
        }
    }
}

// ---------------------------------------------------------------------------
// Launch: probe/zero + adjacency build + 2 SAGE layers. 6 kernels total.
// Inputs: x, src, dst, W_self1, W_neigh1, b1, W_self2, W_neigh2, b2
// ---------------------------------------------------------------------------
extern "C" void kernel_launch(void* const* d_in, const int* in_sizes, int n_in,
                              void* d_out, int out_size) {
    const float* x   = (const float*)d_in[0];
    const void*  src = d_in[1];
    const void*  dst = d_in[2];
    const float* Ws1 = (const float*)d_in[3];
    const float* Wn1 = (const float*)d_in[4];
    const float* b1  = (const float*)d_in[5];
    const float* Ws2 = (const float*)d_in[6];
    const float* Wn2 = (const float*)d_in[7];
    const float* b2  = (const float*)d_in[8];
    float* out = (float*)d_out;

    int N = in_sizes[0] / D;
    int E = in_sizes[1];

    int* cur = (int*)d_out;   // degree counters in harness-allocated memory

    const int TPB = 256;
    int ngrid = (N + TPB - 1) / TPB;
    int egrid = (E + TPB - 1) / TPB;
    int ggrid = ((N * 16) + TPB - 1) / TPB;   // gather: 16 threads/node
    int ntiles = (N + 127) / 128;             // 128-row tiles
    int mgrid = ntiles < 296 ? ntiles : 296;  // 2 blocks/SM persistent

    const int GEMM_SMEM = 96 * 1024;   // 32KB weights + 64KB rows
    cudaFuncSetAttribute(gemm_kernel,
                         cudaFuncAttributeMaxDynamicSharedMemorySize, GEMM_SMEM);

    // ---- Probe + zero counters, then single-pass adjacency build ----
    probe_zero_kernel<<<ngrid + 1, TPB>>>((const unsigned*)dst, E, cur, N);
    fill_adj_kernel<<<egrid, TPB>>>(src, dst, cur, E, N);

    // ---- Layer 1 ----
    gather_kernel<<<ggrid, TPB>>>(x, cur, N, /*use_h1=*/0);
    gemm_kernel<<<mgrid, TPB, GEMM_SMEM>>>(x, Ws1, Wn1, b1, out, N, ntiles,
                                           /*use_h1=*/0, /*out_is_h1=*/1);

    // ---- Layer 2 ----
    gather_kernel<<<ggrid, TPB>>>(x, cur, N, /*use_h1=*/1);
    gemm_kernel<<<mgrid, TPB, GEMM_SMEM>>>(x, Ws2, Wn2, b2, out, N, ntiles,
                                           /*use_h1=*/1, /*out_is_h1=*/0);
}